// round 2
// baseline (speedup 1.0000x reference)
#include <cuda_runtime.h>

#define HH_ 2048
#define WW_ 2048
#define CC_ 3
#define RR_ 2                       // KSIZE
#define HV_ (HH_ - 2*RR_ + 1)       // 2045
#define WV_ (WW_ - 2*RR_ + 1)       // 2045
#define HWTOT (HH_*WW_)
#define NELEM (HH_*WW_*CC_)
#define SRADII_MAX 589824           // 768^2
#define SCLEAN_MAX 586756           // 766^2
#define RAD_ 8

// Scratch (device globals — no allocation allowed in kernel_launch)
__device__ unsigned long long g_packed[HWTOT];   // (order+1)<<32 | src
__device__ float g_swapped[NELEM];               // swapped image, pre-divided by 255
__device__ float g_tmp[NELEM];                   // after horizontal blur

// Gaussian weights, sigma=2, truncate=4 -> radius 8, normalized (float32)
__constant__ float c_w[RAD_+1] = {
    0.19947464f, 0.17603575f, 0.12098747f, 0.06475993f,
    0.02699595f, 0.00876430f, 0.00221596f, 0.00043635f, 0.00006692f
};

__global__ void k_init() {
    int i = blockIdx.x * blockDim.x + threadIdx.x;
    if (i < HWTOT) g_packed[i] = 0ull;
}

// One thread per valid-region pixel (h,w) in [0,2045)^2 (offset by R in image coords).
// If outside the big radius, emit 2 iterations x 2 packed atomicMax writes.
__global__ void k_scatter(const int* __restrict__ off) {
    int w = blockIdx.x * blockDim.x + threadIdx.x;
    int h = blockIdx.y;
    if (w >= WV_) return;
    int hh = h + RR_, ww = w + RR_;
    int dx = 1024 - ww, dy = 1024 - hh;
    int d2 = dx*dx + dy*dy;
    if (d2 < SRADII_MAX) return;

    int lin   = hh * WW_ + ww;
    int local = h * WV_ + w;
    #pragma unroll
    for (int i = 0; i < 2; i++) {
        int oidx = (i * (HV_*WV_) + local) * 2;
        int dh = off[oidx + 0];
        int dw = off[oidx + 1];
        int lin2 = (hh + dh) * WW_ + (ww + dw);
        // order o1 = i*2*HV*WV + 2*local ; o2 = o1+1 ; store order+1 so 0 == "no write"
        unsigned long long o1p1 = (unsigned long long)(i * 2 * (HV_*WV_) + 2*local + 1);
        unsigned long long p1 = (o1p1       << 32) | (unsigned int)lin2;  // tgt=lin,  src=lin2
        unsigned long long p2 = ((o1p1 + 1) << 32) | (unsigned int)lin;   // tgt=lin2, src=lin
        atomicMax(&g_packed[lin],  p1);
        atomicMax(&g_packed[lin2], p2);
    }
}

// Resolve winner, gather from original image, pre-scale by 1/255.
__global__ void k_gather(const float* __restrict__ img) {
    int p = blockIdx.x * blockDim.x + threadIdx.x;
    if (p >= HWTOT) return;
    unsigned long long pk = g_packed[p];
    int src = pk ? (int)(unsigned int)(pk & 0xffffffffull) : p;
    const float inv = 1.0f / 255.0f;
    float r = img[src*3+0], g = img[src*3+1], b = img[src*3+2];
    g_swapped[p*3+0] = r * inv;
    g_swapped[p*3+1] = g * inv;
    g_swapped[p*3+2] = b * inv;
}

// Horizontal blur (taps along w, stride 3 floats), edge clamp.
__global__ void k_blur_h() {
    int idx = blockIdx.x * blockDim.x + threadIdx.x;
    if (idx >= NELEM) return;
    int c   = idx % 3;
    int pix = idx / 3;
    int w   = pix % WW_;
    int rowbase = (pix - w) * 3;     // h*W*3
    float acc = 0.0f;
    #pragma unroll
    for (int t = -RAD_; t <= RAD_; t++) {
        int x = w + t;
        x = (x < 0) ? 0 : ((x > WW_-1) ? WW_-1 : x);
        acc += c_w[t < 0 ? -t : t] * g_swapped[rowbase + x*3 + c];
    }
    g_tmp[idx] = acc;
}

// Vertical blur + clip*255 + clean-mask select against original image.
__global__ void k_blur_v_final(const float* __restrict__ img, float* __restrict__ out) {
    int idx = blockIdx.x * blockDim.x + threadIdx.x;
    if (idx >= NELEM) return;
    int c   = idx % 3;
    int pix = idx / 3;
    int w   = pix % WW_;
    int h   = pix / WW_;
    float acc = 0.0f;
    #pragma unroll
    for (int t = -RAD_; t <= RAD_; t++) {
        int y = h + t;
        y = (y < 0) ? 0 : ((y > HH_-1) ? HH_-1 : y);
        acc += c_w[t < 0 ? -t : t] * g_tmp[(y * WW_ + w) * 3 + c];
    }
    float blurred = fminf(fmaxf(acc, 0.0f), 1.0f) * 255.0f;
    bool clean = false;
    if (h >= RR_ && h <= HH_-RR_ && w >= RR_ && w <= WW_-RR_) {
        int dx = 1024 - w, dy = 1024 - h;
        clean = (dx*dx + dy*dy) < SCLEAN_MAX;
    }
    out[idx] = clean ? img[idx] : blurred;
}

extern "C" void kernel_launch(void* const* d_in, const int* in_sizes, int n_in,
                              void* d_out, int out_size) {
    // Robust input binding: img has NELEM f32 elements, offsets 2*2045*2045*2 i32.
    const float* img;
    const int*   off;
    if (in_sizes[0] == NELEM) {
        img = (const float*)d_in[0];
        off = (const int*)d_in[1];
    } else {
        img = (const float*)d_in[1];
        off = (const int*)d_in[0];
    }
    float* out = (float*)d_out;

    k_init<<<(HWTOT + 255) / 256, 256>>>();

    dim3 sg((WV_ + 255) / 256, HV_);
    k_scatter<<<sg, 256>>>(off);

    k_gather<<<(HWTOT + 255) / 256, 256>>>(img);

    k_blur_h<<<(NELEM + 255) / 256, 256>>>();

    k_blur_v_final<<<(NELEM + 255) / 256, 256>>>(img, out);
}

// round 5
// speedup vs baseline: 2.0648x; 2.0648x over previous
#include <cuda_runtime.h>

#define HW (2048*2048)
#define SRADII_MAX 589824   // 768^2
#define SCLEAN_MAX 586756   // 766^2
#define RSKIP2     562500   // 750^2 : safe skip radius (750 + ~11.3 blur reach < 766)

// Scratch
__device__ unsigned long long g_packed[HW];  // (order+1)<<32 | src
__device__ float g_plane[3*HW];              // gathered, /255, planar
__device__ float g_tmp[3*HW];                // after horizontal blur, planar

// Gaussian sigma=2, truncate=4 -> radius 8 ; weight for tap offset o is c_w[|o|]
__constant__ float c_w[9] = {
    0.19947464f, 0.17603575f, 0.12098747f, 0.06475993f,
    0.02699595f, 0.00876430f, 0.00221596f, 0.00043635f, 0.00006692f
};

__device__ __forceinline__ float wtap(int k) {   // k in [0,16], offset k-8
    return c_w[k < 8 ? 8 - k : k - 8];
}

// ---------------------------------------------------------------- scatter
__global__ void k_scatter(const int2* __restrict__ off) {
    int w = blockIdx.x * blockDim.x + threadIdx.x;
    int h = blockIdx.y;
    if (w >= 2045) return;
    int hh = h + 2, ww = w + 2;
    int dx = 1024 - ww, dy = 1024 - hh;
    if (dx*dx + dy*dy < SRADII_MAX) return;

    int lin   = hh * 2048 + ww;
    int local = h * 2045 + w;
    #pragma unroll
    for (int i = 0; i < 2; i++) {
        int2 o = off[i * (2045*2045) + local];           // (dh, dw)
        int lin2 = (hh + o.x) * 2048 + (ww + o.y);
        unsigned long long o1p1 = (unsigned long long)(i * 2 * (2045*2045) + 2*local + 1);
        atomicMax(&g_packed[lin],  (o1p1       << 32) | (unsigned)lin2);
        atomicMax(&g_packed[lin2], ((o1p1 + 1) << 32) | (unsigned)lin);
    }
}

// ---------------------------------------------------------------- gather -> planar
// grid (8, 2048), block 256 : one 256-pixel row tile per block
__global__ void k_gather(const float* __restrict__ img) {
    int h  = blockIdx.y;
    int x0 = blockIdx.x << 8;
    int dy = 1024 - h;
    int dxa = 1024 - x0, dxb = 1024 - (x0 + 255);
    if (max(dxa*dxa, dxb*dxb) + dy*dy < RSKIP2) return;   // deep-clean: never consumed

    int p = h * 2048 + x0 + threadIdx.x;
    unsigned long long pk = g_packed[p];
    int src = pk ? (int)(pk & 0xffffffffull) : p;
    const float inv = 1.0f / 255.0f;
    g_plane[p]          = img[src*3 + 0] * inv;
    g_plane[HW   + p]   = img[src*3 + 1] * inv;
    g_plane[2*HW + p]   = img[src*3 + 2] * inv;
}

// ---------------------------------------------------------------- horizontal blur (planar)
// grid (4, 2048, 3), block 128 : thread computes float4 (4 pixels) of one channel row
__global__ void k_blur_h() {
    int h = blockIdx.y, c = blockIdx.z;
    int x  = ((blockIdx.x << 7) + threadIdx.x) << 2;
    int x0 = blockIdx.x << 9;
    int dy = 1024 - h;
    int dxa = 1024 - x0, dxb = 1024 - (x0 + 511);
    if (max(dxa*dxa, dxb*dxb) + dy*dy < RSKIP2) return;

    const float* row = g_plane + c*HW + h*2048;
    float v[20];
    if (x >= 8 && x <= 2036) {
        const float4* r4 = (const float4*)(row + x - 8);
        #pragma unroll
        for (int k = 0; k < 5; k++) {
            float4 t = r4[k];
            v[4*k] = t.x; v[4*k+1] = t.y; v[4*k+2] = t.z; v[4*k+3] = t.w;
        }
    } else {
        #pragma unroll
        for (int k = 0; k < 20; k++) {
            int xx = x - 8 + k;
            xx = xx < 0 ? 0 : (xx > 2047 ? 2047 : xx);
            v[k] = row[xx];
        }
    }
    float4 o;
    float* op = (float*)&o;
    #pragma unroll
    for (int j = 0; j < 4; j++) {
        float acc = 0.0f;
        #pragma unroll
        for (int k = 0; k < 17; k++) acc += wtap(k) * v[j + k];
        op[j] = acc;
    }
    *(float4*)(g_tmp + c*HW + h*2048 + x) = o;
}

// ---------------------------------------------------------------- vertical blur + finalize
// grid (4, 2048), block 128 : thread does 4 pixels x 3 channels, writes 12 interleaved floats
__global__ void k_blur_v_final(const float* __restrict__ img, float* __restrict__ out) {
    int h  = blockIdx.y;
    int x  = ((blockIdx.x << 7) + threadIdx.x) << 2;
    int x0 = blockIdx.x << 9;
    int dy = 1024 - h, dy2 = dy*dy;
    int dxa = 1024 - x0, dxb = 1024 - (x0 + 511);
    int maxdx2 = max(dxa*dxa, dxb*dxb);
    int mindx2 = (x0 <= 1024 && 1024 <= x0 + 511) ? 0 : min(dxa*dxa, dxb*dxb);
    int maxd2 = maxdx2 + dy2;
    int mind2 = mindx2 + dy2;
    int base3 = (h * 2048 + x) * 3;

    if (maxd2 < SCLEAN_MAX) {                 // whole tile clean: pure copy
        const float4* s = (const float4*)(img + base3);
        float4*       d = (float4*)(out + base3);
        d[0] = s[0]; d[1] = s[1]; d[2] = s[2];
        return;
    }

    float acc[3][4];
    #pragma unroll
    for (int c = 0; c < 3; c++)
        #pragma unroll
        for (int j = 0; j < 4; j++) acc[c][j] = 0.0f;

    bool interior = (h >= 8 && h <= 2039);
    #pragma unroll
    for (int c = 0; c < 3; c++) {
        const float* pl = g_tmp + c*HW + x;
        if (interior) {
            #pragma unroll
            for (int k = 0; k < 17; k++) {
                float4 rv = *(const float4*)(pl + (h - 8 + k) * 2048);
                float wt = wtap(k);
                acc[c][0] += wt * rv.x; acc[c][1] += wt * rv.y;
                acc[c][2] += wt * rv.z; acc[c][3] += wt * rv.w;
            }
        } else {
            #pragma unroll
            for (int k = 0; k < 17; k++) {
                int y = h - 8 + k;
                y = y < 0 ? 0 : (y > 2047 ? 2047 : y);
                float4 rv = *(const float4*)(pl + y * 2048);
                float wt = wtap(k);
                acc[c][0] += wt * rv.x; acc[c][1] += wt * rv.y;
                acc[c][2] += wt * rv.z; acc[c][3] += wt * rv.w;
            }
        }
    }

    float res[4][3];
    #pragma unroll
    for (int j = 0; j < 4; j++)
        #pragma unroll
        for (int c = 0; c < 3; c++)
            res[j][c] = fminf(fmaxf(acc[c][j], 0.0f), 1.0f) * 255.0f;

    if (mind2 < SCLEAN_MAX) {                 // mixed tile: per-pixel clean select
        float4 i0 = *(const float4*)(img + base3);
        float4 i1 = *(const float4*)(img + base3 + 4);
        float4 i2 = *(const float4*)(img + base3 + 8);
        float im[12] = {i0.x,i0.y,i0.z,i0.w, i1.x,i1.y,i1.z,i1.w, i2.x,i2.y,i2.z,i2.w};
        #pragma unroll
        for (int j = 0; j < 4; j++) {
            int dxj = 1024 - (x + j);
            if (dy2 + dxj*dxj < SCLEAN_MAX) {
                res[j][0] = im[3*j+0]; res[j][1] = im[3*j+1]; res[j][2] = im[3*j+2];
            }
        }
    }

    float4* d = (float4*)(out + base3);
    d[0] = make_float4(res[0][0], res[0][1], res[0][2], res[1][0]);
    d[1] = make_float4(res[1][1], res[1][2], res[2][0], res[2][1]);
    d[2] = make_float4(res[2][2], res[3][0], res[3][1], res[3][2]);
}

extern "C" void kernel_launch(void* const* d_in, const int* in_sizes, int n_in,
                              void* d_out, int out_size) {
    const float* img;
    const int*   off;
    if (in_sizes[0] == 2048*2048*3) {
        img = (const float*)d_in[0];
        off = (const int*)d_in[1];
    } else {
        img = (const float*)d_in[1];
        off = (const int*)d_in[0];
    }
    float* out = (float*)d_out;

    void* pk = nullptr;
    cudaGetSymbolAddress(&pk, g_packed);
    cudaMemsetAsync(pk, 0, sizeof(unsigned long long) * HW, 0);

    dim3 sg((2045 + 255) / 256, 2045);
    k_scatter<<<sg, 256>>>((const int2*)off);

    k_gather<<<dim3(8, 2048), 256>>>(img);

    k_blur_h<<<dim3(4, 2048, 3), 128>>>();

    k_blur_v_final<<<dim3(4, 2048), 128>>>(img, out);
}

// round 7
// speedup vs baseline: 2.2467x; 1.0881x over previous
#include <cuda_runtime.h>

#define HW (2048*2048)
#define SRADII_MAX 589824   // 768^2
#define SCLEAN_MAX 586756   // 766^2
#define RSKIP2     562500   // 750^2 : safe skip radius (750 + ~11.3 blur reach < 766)
#define RGATE2     585225   // 765^2 : only px with d2>=this can be scatter targets (768 - 2*sqrt(2))

// Scratch
__device__ unsigned long long g_packed[HW];  // (order+1)<<32 | src
__device__ float g_plane[3*HW];              // gathered, /255, planar
__device__ float g_tmp[3*HW];                // after horizontal blur, planar

// Gaussian sigma=2, truncate=4 -> radius 8 ; weight for tap offset o is c_w[|o|]
__constant__ float c_w[9] = {
    0.19947464f, 0.17603575f, 0.12098747f, 0.06475993f,
    0.02699595f, 0.00876430f, 0.00221596f, 0.00043635f, 0.00006692f
};

__device__ __forceinline__ float wtap(int k) {   // k in [0,16], offset k-8
    return c_w[k < 8 ? 8 - k : k - 8];
}

// ---------------------------------------------------------------- scatter
__global__ void k_scatter(const int2* __restrict__ off) {
    int w = blockIdx.x * blockDim.x + threadIdx.x;
    int h = blockIdx.y;
    if (w >= 2045) return;
    int hh = h + 2, ww = w + 2;
    int dx = 1024 - ww, dy = 1024 - hh;
    if (dx*dx + dy*dy < SRADII_MAX) return;

    int lin   = hh * 2048 + ww;
    int local = h * 2045 + w;
    #pragma unroll
    for (int i = 0; i < 2; i++) {
        int2 o = off[i * (2045*2045) + local];           // (dh, dw)
        int lin2 = (hh + o.x) * 2048 + (ww + o.y);
        unsigned long long o1p1 = (unsigned long long)(i * 2 * (2045*2045) + 2*local + 1);
        atomicMax(&g_packed[lin],  (o1p1       << 32) | (unsigned)lin2);
        atomicMax(&g_packed[lin2], ((o1p1 + 1) << 32) | (unsigned)lin);
    }
}

// ---------------------------------------------------------------- gather -> planar
// grid (8, 2048), block 256 : one 256-pixel row tile per block
__global__ void k_gather(const float* __restrict__ img) {
    int h  = blockIdx.y;
    int x0 = blockIdx.x << 8;
    int dy = 1024 - h;
    int dy2 = dy*dy;
    int dxa = 1024 - x0, dxb = 1024 - (x0 + 255);
    if (max(dxa*dxa, dxb*dxb) + dy2 < RSKIP2) return;   // deep-clean: never consumed

    int xw = x0 + threadIdx.x;
    int p  = h * 2048 + xw;
    int dx = 1024 - xw;
    int src = p;
    if (dx*dx + dy2 >= RGATE2) {                        // only these can be scatter targets
        unsigned long long pk = g_packed[p];
        if (pk) src = (int)(pk & 0xffffffffull);
    }
    const float inv = 1.0f / 255.0f;
    g_plane[p]          = img[src*3 + 0] * inv;
    g_plane[HW   + p]   = img[src*3 + 1] * inv;
    g_plane[2*HW + p]   = img[src*3 + 2] * inv;
}

// ---------------------------------------------------------------- horizontal blur (planar)
// grid (4, 2048, 3), block 128 : thread computes float4 (4 pixels) of one channel row
__global__ void k_blur_h() {
    int h = blockIdx.y, c = blockIdx.z;
    int x  = ((blockIdx.x << 7) + threadIdx.x) << 2;
    int x0 = blockIdx.x << 9;
    int dy = 1024 - h;
    int dxa = 1024 - x0, dxb = 1024 - (x0 + 511);
    if (max(dxa*dxa, dxb*dxb) + dy*dy < RSKIP2) return;

    const float* row = g_plane + c*HW + h*2048;
    float v[20];
    if (x >= 8 && x <= 2036) {
        const float4* r4 = (const float4*)(row + x - 8);
        #pragma unroll
        for (int k = 0; k < 5; k++) {
            float4 t = r4[k];
            v[4*k] = t.x; v[4*k+1] = t.y; v[4*k+2] = t.z; v[4*k+3] = t.w;
        }
    } else {
        #pragma unroll
        for (int k = 0; k < 20; k++) {
            int xx = x - 8 + k;
            xx = xx < 0 ? 0 : (xx > 2047 ? 2047 : xx);
            v[k] = row[xx];
        }
    }
    float4 o;
    float* op = (float*)&o;
    #pragma unroll
    for (int j = 0; j < 4; j++) {
        float acc = 0.0f;
        #pragma unroll
        for (int k = 0; k < 17; k++) acc += wtap(k) * v[j + k];
        op[j] = acc;
    }
    *(float4*)(g_tmp + c*HW + h*2048 + x) = o;
}

// ---------------------------------------------------------------- vertical blur + finalize
// grid (4, 512), block 128 : thread does a 4-row x 4-px x 3-ch brick.
// Streams 20 input rows through registers, accumulating into 4 output rows
// simultaneously -> 60 float4 loads for 48 outputs (was 51 loads / 12 outputs).
__global__ void k_blur_v_final(const float* __restrict__ img, float* __restrict__ out) {
    int x  = ((blockIdx.x << 7) + threadIdx.x) << 2;
    int x0 = blockIdx.x << 9;
    int y0 = blockIdx.y << 2;

    int dxa = 1024 - x0, dxb = 1024 - (x0 + 511);
    int maxdx2 = max(dxa*dxa, dxb*dxb);
    int mindx2 = (x0 <= 1024 && 1024 <= x0 + 511) ? 0 : min(dxa*dxa, dxb*dxb);
    int dya = 1024 - y0, dyb = 1024 - (y0 + 3);
    int maxdy2 = max(dya*dya, dyb*dyb);
    int mindy2 = (y0 <= 1024 && 1024 <= y0 + 3) ? 0 : min(dya*dya, dyb*dyb);

    if (maxdx2 + maxdy2 < SCLEAN_MAX) {       // whole brick clean: pure copy
        #pragma unroll
        for (int r = 0; r < 4; r++) {
            int b3 = ((y0 + r) * 2048 + x) * 3;
            const float4* s = (const float4*)(img + b3);
            float4*       d = (float4*)(out + b3);
            d[0] = s[0]; d[1] = s[1]; d[2] = s[2];
        }
        return;
    }

    float acc[3][4][4];                       // [ch][row][px]
    #pragma unroll
    for (int c = 0; c < 3; c++)
        #pragma unroll
        for (int r = 0; r < 4; r++)
            #pragma unroll
            for (int j = 0; j < 4; j++) acc[c][r][j] = 0.0f;

    // Stream 20 input rows; row k feeds output row r at tap (k - r).
    #pragma unroll
    for (int k = 0; k < 20; k++) {
        int y = y0 - 8 + k;
        y = y < 0 ? 0 : (y > 2047 ? 2047 : y);
        #pragma unroll
        for (int c = 0; c < 3; c++) {
            float4 rv = *(const float4*)(g_tmp + c*HW + y * 2048 + x);
            #pragma unroll
            for (int r = 0; r < 4; r++) {
                int t = k - r;
                if (t >= 0 && t <= 16) {
                    float wt = wtap(t);
                    acc[c][r][0] += wt * rv.x; acc[c][r][1] += wt * rv.y;
                    acc[c][r][2] += wt * rv.z; acc[c][r][3] += wt * rv.w;
                }
            }
        }
    }

    bool mixed = (mindx2 + mindy2) < SCLEAN_MAX;
    #pragma unroll
    for (int r = 0; r < 4; r++) {
        int yr   = y0 + r;
        int dyr  = 1024 - yr;
        int dy2r = dyr * dyr;
        int b3   = (yr * 2048 + x) * 3;

        float res[12];
        #pragma unroll
        for (int j = 0; j < 4; j++)
            #pragma unroll
            for (int c = 0; c < 3; c++)
                res[3*j + c] = fminf(fmaxf(acc[c][r][j], 0.0f), 1.0f) * 255.0f;

        if (mixed) {
            float4 i0 = *(const float4*)(img + b3);
            float4 i1 = *(const float4*)(img + b3 + 4);
            float4 i2 = *(const float4*)(img + b3 + 8);
            float im[12] = {i0.x,i0.y,i0.z,i0.w, i1.x,i1.y,i1.z,i1.w, i2.x,i2.y,i2.z,i2.w};
            #pragma unroll
            for (int j = 0; j < 4; j++) {
                int dxj = 1024 - (x + j);
                if (dy2r + dxj*dxj < SCLEAN_MAX) {
                    res[3*j+0] = im[3*j+0]; res[3*j+1] = im[3*j+1]; res[3*j+2] = im[3*j+2];
                }
            }
        }

        float4* d = (float4*)(out + b3);
        d[0] = make_float4(res[0], res[1], res[2],  res[3]);
        d[1] = make_float4(res[4], res[5], res[6],  res[7]);
        d[2] = make_float4(res[8], res[9], res[10], res[11]);
    }
}

extern "C" void kernel_launch(void* const* d_in, const int* in_sizes, int n_in,
                              void* d_out, int out_size) {
    const float* img;
    const int*   off;
    if (in_sizes[0] == 2048*2048*3) {
        img = (const float*)d_in[0];
        off = (const int*)d_in[1];
    } else {
        img = (const float*)d_in[1];
        off = (const int*)d_in[0];
    }
    float* out = (float*)d_out;

    void* pk = nullptr;
    cudaGetSymbolAddress(&pk, g_packed);
    cudaMemsetAsync(pk, 0, sizeof(unsigned long long) * HW, 0);

    dim3 sg((2045 + 255) / 256, 2045);
    k_scatter<<<sg, 256>>>((const int2*)off);

    k_gather<<<dim3(8, 2048), 256>>>(img);

    k_blur_h<<<dim3(4, 2048, 3), 128>>>();

    k_blur_v_final<<<dim3(4, 512), 128>>>(img, out);
}

// round 8
// speedup vs baseline: 2.6137x; 1.1633x over previous
#include <cuda_runtime.h>

#define HW (2048*2048)
#define SRADII_MAX 589824   // 768^2
#define SCLEAN_MAX 586756   // 766^2
#define RGATE2     585225   // 765^2 : only px with d2>=this can be scatter targets (768 - 2*sqrt(2) = 765.17)

__device__ unsigned long long g_packed[HW];  // (order+1)<<32 | src

// Gaussian sigma=2, truncate=4 -> radius 8 ; weight for tap offset o is c_w[|o|]
__constant__ float c_w[9] = {
    0.19947464f, 0.17603575f, 0.12098747f, 0.06475993f,
    0.02699595f, 0.00876430f, 0.00221596f, 0.00043635f, 0.00006692f
};

__device__ __forceinline__ float wtap(int k) {   // k in [0,16], offset k-8
    return c_w[k < 8 ? 8 - k : k - 8];
}

// ---------------------------------------------------------------- scatter
__global__ void k_scatter(const int2* __restrict__ off) {
    int w = blockIdx.x * blockDim.x + threadIdx.x;
    int h = blockIdx.y;
    if (w >= 2045) return;
    int hh = h + 2, ww = w + 2;
    int dx = 1024 - ww, dy = 1024 - hh;
    if (dx*dx + dy*dy < SRADII_MAX) return;

    int lin   = hh * 2048 + ww;
    int local = h * 2045 + w;
    #pragma unroll
    for (int i = 0; i < 2; i++) {
        int2 o = off[i * (2045*2045) + local];           // (dh, dw)
        int lin2 = (hh + o.x) * 2048 + (ww + o.y);
        unsigned long long o1p1 = (unsigned long long)(i * 2 * (2045*2045) + 2*local + 1);
        atomicMax(&g_packed[lin],  (o1p1       << 32) | (unsigned)lin2);
        atomicMax(&g_packed[lin2], ((o1p1 + 1) << 32) | (unsigned)lin);
    }
}

// ---------------------------------------------------------------- fused gather + H blur + V blur + finalize
// grid (32, 128), block 256. Output tile 64x16, halo 80x32 in smem.
__global__ __launch_bounds__(256) void k_fused(const float* __restrict__ img,
                                               float* __restrict__ out) {
    int x0 = blockIdx.x << 6;
    int y0 = blockIdx.y << 4;
    int tid = threadIdx.x;

    int dxa = 1024 - x0, dxb = 1024 - (x0 + 63);
    int maxdx2 = max(dxa*dxa, dxb*dxb);
    int mindx2 = (x0 <= 1024 && 1024 <= x0 + 63) ? 0 : min(dxa*dxa, dxb*dxb);
    int dya = 1024 - y0, dyb = 1024 - (y0 + 15);
    int maxdy2 = max(dya*dya, dyb*dyb);
    int mindy2 = (y0 <= 1024 && 1024 <= y0 + 15) ? 0 : min(dya*dya, dyb*dyb);

    if (maxdx2 + maxdy2 < SCLEAN_MAX) {       // whole tile clean: pure float4 copy
        int fb = ((y0 * 2048 + x0) * 3) >> 2; // x0 mult of 64 -> divisible by 4
        const float4* s = (const float4*)img;
        float4*       d = (float4*)out;
        #pragma unroll
        for (int i = 0; i < 3; i++) {
            int j  = tid + (i << 8);          // 0..767
            int row = j / 48, col = j - row * 48;
            int fi = fb + row * 1536 + col;   // 1536 float4 per image row
            d[fi] = s[fi];
        }
        return;
    }

    __shared__ float s_in[3][32][80];         // gathered /255, halo tile
    __shared__ float s_h[32][64];             // H-blur result, one channel at a time

    // ---- load + inline gather (2560 halo pixels, 10 per thread) ----
    const float inv = 1.0f / 255.0f;
    #pragma unroll
    for (int it = 0; it < 10; it++) {
        int i  = tid + (it << 8);
        int hy = i / 80, hx = i - hy * 80;
        int gy = y0 - 8 + hy; gy = gy < 0 ? 0 : (gy > 2047 ? 2047 : gy);
        int gx = x0 - 8 + hx; gx = gx < 0 ? 0 : (gx > 2047 ? 2047 : gx);
        int p  = gy * 2048 + gx;
        int src = p;
        int ddx = 1024 - gx, ddy = 1024 - gy;
        if (ddx*ddx + ddy*ddy >= RGATE2) {    // only these can be scatter targets
            unsigned long long pk = g_packed[p];
            if (pk) src = (int)(pk & 0xffffffffull);
        }
        s_in[0][hy][hx] = img[src*3 + 0] * inv;
        s_in[1][hy][hx] = img[src*3 + 1] * inv;
        s_in[2][hy][hx] = img[src*3 + 2] * inv;
    }
    __syncthreads();

    bool mixed = (mindx2 + mindy2) < SCLEAN_MAX;
    int yy  = tid >> 3;                       // H pass: row 0..31
    int xb  = (tid & 7) << 3;                 // H pass: col block 0,8,..,56
    int xo  = tid & 63;                       // V pass: column
    int grp = tid >> 6;                       // V pass: 4-row group 0..3
    int px  = x0 + xo;
    int dxp2 = (1024 - px) * (1024 - px);

    #pragma unroll
    for (int c = 0; c < 3; c++) {
        // ---- H blur: 8 outputs from 24 inputs (6 x LDS.128) ----
        float v[24];
        const float4* rp = (const float4*)&s_in[c][yy][xb];
        #pragma unroll
        for (int q = 0; q < 6; q++) {
            float4 t = rp[q];
            v[4*q] = t.x; v[4*q+1] = t.y; v[4*q+2] = t.z; v[4*q+3] = t.w;
        }
        float ho[8];
        #pragma unroll
        for (int j = 0; j < 8; j++) {
            float a = 0.0f;
            #pragma unroll
            for (int k = 0; k < 17; k++) a += wtap(k) * v[j + k];
            ho[j] = a;
        }
        *(float4*)&s_h[yy][xb]     = make_float4(ho[0], ho[1], ho[2], ho[3]);
        *(float4*)&s_h[yy][xb + 4] = make_float4(ho[4], ho[5], ho[6], ho[7]);
        __syncthreads();

        // ---- V blur: stream 20 rows, accumulate 4 output rows ----
        float a0 = 0.f, a1 = 0.f, a2 = 0.f, a3 = 0.f;
        #pragma unroll
        for (int k = 0; k < 20; k++) {
            float val = s_h[(grp << 2) + k][xo];
            if (k <= 16)           a0 += wtap(k)     * val;
            if (k >= 1 && k <= 17) a1 += wtap(k - 1) * val;
            if (k >= 2 && k <= 18) a2 += wtap(k - 2) * val;
            if (k >= 3)            a3 += wtap(k - 3) * val;
        }
        float accs[4] = {a0, a1, a2, a3};
        #pragma unroll
        for (int r = 0; r < 4; r++) {
            int y  = y0 + (grp << 2) + r;
            int oi = (y * 2048 + px) * 3 + c;
            float bv = fminf(fmaxf(accs[r], 0.0f), 1.0f) * 255.0f;
            if (mixed) {
                int dyp = 1024 - y;
                if (dxp2 + dyp * dyp < SCLEAN_MAX) bv = img[oi];
            }
            out[oi] = bv;
        }
        __syncthreads();                      // s_h reused by next channel
    }
}

extern "C" void kernel_launch(void* const* d_in, const int* in_sizes, int n_in,
                              void* d_out, int out_size) {
    const float* img;
    const int*   off;
    if (in_sizes[0] == 2048*2048*3) {
        img = (const float*)d_in[0];
        off = (const int*)d_in[1];
    } else {
        img = (const float*)d_in[1];
        off = (const int*)d_in[0];
    }
    float* out = (float*)d_out;

    void* pk = nullptr;
    cudaGetSymbolAddress(&pk, g_packed);
    cudaMemsetAsync(pk, 0, sizeof(unsigned long long) * HW, 0);

    dim3 sg((2045 + 255) / 256, 2045);
    k_scatter<<<sg, 256>>>((const int2*)off);

    k_fused<<<dim3(32, 128), 256>>>(img, out);
}